// round 15
// baseline (speedup 1.0000x reference)
#include <cuda_runtime.h>
#include <cuda_fp16.h>

#define HW    160
#define NIMG  32
#define NBITS 128
#define SW    168
#define SW2   (SW / 2)         // 84 pair-entries per row
#define TH    16
#define TROWS 22
#define TILEN (TROWS * SW)     // 3696 column indices
#define PAIRS (TILEN / 2)      // 1848 u64 entries per parity tile
#define BITG  8
#define NTHR  320
#define RR    4                // rows per thread (320 thr = 80 pairs x 4 rgs)

struct __align__(16) BitH {
    __half2 fx1, fx2, B1, A1, B2n, A2n, c;   // 28 B
    int off1, off2;                           // y1*SW + x1 per interp
    int pad;                                  // -> 40 B
};

__device__ __forceinline__ __half2 hfma2_sat(__half2 a, __half2 b, __half2 c) {
    __half2 r;
    asm("fma.rn.sat.f16x2 %0, %1, %2, %3;"
        : "=r"(*(unsigned*)&r)
        : "r"(*(unsigned*)&a), "r"(*(unsigned*)&b), "r"(*(unsigned*)&c));
    return r;
}

__device__ __forceinline__ void stcs64(float* p, float2 v) {
    asm volatile("st.global.cs.v2.f32 [%0], {%1, %2};"
                 :: "l"(p), "f"(v.x), "f"(v.y) : "memory");
}

// ---------------------------------------------------------------------------
// Single fused kernel. Block = (16-row tile, 8-bit group, image), 320 thr =
// 80 column-pairs x 4 row-groups (4 rows each); 5120 short blocks (minimal
// wave-quantization + drain tail — the R11-verified granularity lever).
// Delta pair-tiles: EA[j]=(p[2j],p[2j+1],d[2j],d[2j+1]), EB[j]= same at
// s=2j+1; consecutive lanes hit consecutive u64 entries (dense LDS.64).
// SOFTWARE PIPELINE: double-buffered horizontal lerps z[2][RR+1] — the 10
// LDS.64s + conversions of bit b+1 issue before the combine+store of bit b.
// ---------------------------------------------------------------------------
__global__ __launch_bounds__(NTHR) void fern_main(const float* __restrict__ x,
                                                  const float* __restrict__ dx1,
                                                  const float* __restrict__ dx2,
                                                  const float* __restrict__ dy1,
                                                  const float* __restrict__ dy2,
                                                  const float* __restrict__ th,
                                                  float* __restrict__ out) {
    __shared__ __align__(16) uint2 EA[PAIRS];
    __shared__ __align__(16) uint2 EB[PAIRS];
    __shared__ BitH  sp[BITG];
    __shared__ float wred[4];

    int tid = threadIdx.x;
    int h0  = blockIdx.x * TH;
    int bg  = blockIdx.y;
    int n   = blockIdx.z;

    // --- L = max|offset| (warp reductions; identical in every block) -------
    float m = 0.0f;
    if (tid < 128) {
        m = fmaxf(fmaxf(fabsf(dx1[tid]), fabsf(dx2[tid])),
                  fmaxf(fabsf(dy1[tid]), fabsf(dy2[tid])));
    }
#pragma unroll
    for (int o = 16; o; o >>= 1) m = fmaxf(m, __shfl_xor_sync(0xffffffffu, m, o));
    if (tid < 128 && (tid & 31) == 0) wred[tid >> 5] = m;

    // --- fill delta pair-tiles (row-major, cheap indexing) -----------------
    const float* src = x + ((size_t)n * 3 + 1) * (HW * HW);
    for (int j = tid; j < PAIRS; j += NTHR) {
        int r  = j / SW2;                 // one division per entry
        int c  = j - r * SW2;             // pair column 0..83
        int h  = h0 + r - 3;
        int w0 = 2 * c - 3;
        const float* row = src + h * HW;
        bool hok = (unsigned)h < HW;
        float v0 = 0.0f, v1 = 0.0f, v2 = 0.0f, v3 = 0.0f;
        if (hok) {
            if ((unsigned)w0 < HW)        v0 = row[w0];
            if ((unsigned)(w0 + 1) < HW)  v1 = row[w0 + 1];
            if (c != SW2 - 1) {           // c==83: cols land in next row's
                if ((unsigned)(w0 + 2) < HW) v2 = row[w0 + 2];   // left pad = 0
                if ((unsigned)(w0 + 3) < HW) v3 = row[w0 + 3];
            }
        }
        __half h0v = __float2half(v0), h1v = __float2half(v1);
        __half h2v = __float2half(v2);
        __half d0 = __float2half(v1 - v0);
        __half d1 = __float2half(v2 - v1);
        __half d2 = __float2half(v3 - v2);
        uint2 ea, eb;
        *(__half2*)&ea.x = __halves2half2(h0v, h1v);
        *(__half2*)&ea.y = __halves2half2(d0, d1);
        *(__half2*)&eb.x = __halves2half2(h1v, h2v);
        *(__half2*)&eb.y = __halves2half2(d1, d2);
        EA[j] = ea;
        EB[j] = eb;
    }
    __syncthreads();

    // --- per-bit params (reference-exact index math) -----------------------
    if (tid < BITG) {
        float L = fmaxf(fmaxf(wred[0], wred[1]), fmaxf(wred[2], wred[3]));
        int shift = 3 - (int)ceilf(L);
        int bit = bg * BITG + tid;
        BitH bp;
        {
            float dx = dx1[bit], dy = dy1[bit];
            float fdx = floorf(dx), fdy = floorf(dy);
            int x1 = (int)(L + fdx) + shift;    // trunc toward zero == astype(int32)
            int y1 = (int)(L + fdy) + shift;
            x1 = min(max(x1, 0), 5);            // dynamic_slice start clamp
            y1 = min(max(y1, 0), 5);
            bp.off1 = y1 * SW + x1;
            float fx = dx - fdx, fy = dy - fdy;
            bp.fx1 = __float2half2_rn(fx);
            bp.A1  = __float2half2_rn(0.25f * fy);
            bp.B1  = __float2half2_rn(0.25f * (1.0f - fy));
        }
        {
            float dx = dx2[bit], dy = dy2[bit];
            float fdx = floorf(dx), fdy = floorf(dy);
            int x1 = (int)(L + fdx) + shift;
            int y1 = (int)(L + fdy) + shift;
            x1 = min(max(x1, 0), 5);
            y1 = min(max(y1, 0), 5);
            bp.off2 = y1 * SW + x1;
            float fx = dx - fdx, fy = dy - fdy;
            bp.fx2 = __float2half2_rn(fx);
            bp.A2n = __float2half2_rn(-0.25f * fy);
            bp.B2n = __float2half2_rn(-0.25f * (1.0f - fy));
        }
        bp.c = __float2half2_rn(fmaf(-0.25f, th[bit], 0.125f));
        bp.pad = 0;
        sp[tid] = bp;
    }
    __syncthreads();

    // --- main loop (software-pipelined over bits) --------------------------
    int p     = tid % 80;             // column pair
    int wp    = 2 * p;
    int ro0   = (tid / 80) * RR;      // first output row of this thread
    int pbase = p + ro0 * SW2;        // uniform per-thread pair offset

    float* op0 = out + (((size_t)n * NBITS + bg * BITG) * HW + h0 + ro0) * HW + wp;

    __half2 z1[2][RR + 1], z2[2][RR + 1];

    // prologue: bit 0 loads + horizontal lerps
    {
        BitH bq = sp[0];
        const uint2* q1 = ((bq.off1 & 1) ? EB : EA) + (bq.off1 >> 1) + pbase;
        const uint2* q2 = ((bq.off2 & 1) ? EB : EA) + (bq.off2 >> 1) + pbase;
#pragma unroll
        for (int r = 0; r <= RR; ++r) {
            uint2 e1 = q1[r * SW2], e2 = q2[r * SW2];
            z1[0][r] = __hfma2(bq.fx1, *(__half2*)&e1.y, *(__half2*)&e1.x);
            z2[0][r] = __hfma2(bq.fx2, *(__half2*)&e2.y, *(__half2*)&e2.x);
        }
    }

#pragma unroll 2
    for (int b = 0; b < BITG; ++b) {
        int cur = b & 1, nxt = cur ^ 1;

        // prefetch + convert next bit (loads issue before current combine)
        {
            int bn = (b + 1 < BITG) ? (b + 1) : b;   // tail: cheap re-read
            BitH bq = sp[bn];
            const uint2* q1 = ((bq.off1 & 1) ? EB : EA) + (bq.off1 >> 1) + pbase;
            const uint2* q2 = ((bq.off2 & 1) ? EB : EA) + (bq.off2 >> 1) + pbase;
#pragma unroll
            for (int r = 0; r <= RR; ++r) {
                uint2 e1 = q1[r * SW2], e2 = q2[r * SW2];
                z1[nxt][r] = __hfma2(bq.fx1, *(__half2*)&e1.y, *(__half2*)&e1.x);
                z2[nxt][r] = __hfma2(bq.fx2, *(__half2*)&e2.y, *(__half2*)&e2.x);
            }
        }

        // combine + store current bit
        BitH bp = sp[b];
        float* op = op0;
        op0 += HW * HW;

#pragma unroll
        for (int hh = 0; hh < RR; ++hh) {
            __half2 v = __hfma2(bp.B1, z1[cur][hh], bp.c);
            v = __hfma2(bp.A1,  z1[cur][hh + 1], v);
            v = __hfma2(bp.B2n, z2[cur][hh], v);
            v = hfma2_sat(bp.A2n, z2[cur][hh + 1], v);

            stcs64(op + (size_t)hh * HW, __half22float2(v));
        }
    }
}

// ---------------------------------------------------------------------------
extern "C" void kernel_launch(void* const* d_in, const int* in_sizes, int n_in,
                              void* d_out, int out_size) {
    const float* x   = (const float*)d_in[0];
    const float* dx1 = (const float*)d_in[1];
    const float* dx2 = (const float*)d_in[2];
    const float* dy1 = (const float*)d_in[3];
    const float* dy2 = (const float*)d_in[4];
    const float* th  = (const float*)d_in[5];

    dim3 grid(HW / TH, NBITS / BITG, NIMG);
    fern_main<<<grid, NTHR>>>(x, dx1, dx2, dy1, dy2, th, (float*)d_out);
}

// round 16
// speedup vs baseline: 1.6896x; 1.6896x over previous
#include <cuda_runtime.h>
#include <cuda_fp16.h>

#define HW    160
#define NIMG  32
#define NBITS 128
#define SW    168
#define SW2   (SW / 2)         // 84 pair-entries per row
#define TH    16
#define NHT   (HW / TH)        // 10 h-tiles
#define TROWS 22
#define TILEN (TROWS * SW)     // 3696 column indices
#define PAIRS (TILEN / 2)      // 1848 u64 entries per parity tile
#define BITG  16
#define NTHR  320
#define RR    4                // rows per thread (320 thr = 80 pairs x 4 rgs)

struct __align__(16) BitH {
    __half2 fx1, fx2, B1, A1, B2n, A2n, c;   // 28 B
    int off1, off2;                           // y1*SW + x1 per interp
    int pad0, pad1, pad2;                     // -> 48 B (uint4-copyable)
};

__device__ BitH  g_params[NBITS];
__device__ __align__(16) uint2 g_EA[NIMG * NHT * PAIRS];
__device__ __align__(16) uint2 g_EB[NIMG * NHT * PAIRS];

__device__ __forceinline__ __half2 hfma2_sat(__half2 a, __half2 b, __half2 c) {
    __half2 r;
    asm("fma.rn.sat.f16x2 %0, %1, %2, %3;"
        : "=r"(*(unsigned*)&r)
        : "r"(*(unsigned*)&a), "r"(*(unsigned*)&b), "r"(*(unsigned*)&c));
    return r;
}

__device__ __forceinline__ void stcs64(float* p, float2 v) {
    asm volatile("st.global.cs.v2.f32 [%0], {%1, %2};"
                 :: "l"(p), "f"(v.x), "f"(v.y) : "memory");
}

// ---------------------------------------------------------------------------
// Prep: build every delta pair-tile ONCE (was redundantly rebuilt by 8 blocks
// per tile = ~1/3 of runtime), plus the 128 per-bit params.
// ---------------------------------------------------------------------------
__global__ __launch_bounds__(NTHR) void prep_kernel(const float* __restrict__ x,
                                                    const float* __restrict__ dx1,
                                                    const float* __restrict__ dx2,
                                                    const float* __restrict__ dy1,
                                                    const float* __restrict__ dy2,
                                                    const float* __restrict__ th) {
    int tid = threadIdx.x;

    if (blockIdx.x == 0 && blockIdx.y == 0) {
        __shared__ float wred[4];
        float m = 0.0f;
        if (tid < 128) {
            m = fmaxf(fmaxf(fabsf(dx1[tid]), fabsf(dx2[tid])),
                      fmaxf(fabsf(dy1[tid]), fabsf(dy2[tid])));
        }
#pragma unroll
        for (int o = 16; o; o >>= 1) m = fmaxf(m, __shfl_xor_sync(0xffffffffu, m, o));
        if (tid < 128 && (tid & 31) == 0) wred[tid >> 5] = m;
        __syncthreads();
        if (tid < 128) {
            float L = fmaxf(fmaxf(wred[0], wred[1]), fmaxf(wred[2], wred[3]));
            int shift = 3 - (int)ceilf(L);
            BitH bp;
            {
                float dx = dx1[tid], dy = dy1[tid];
                float fdx = floorf(dx), fdy = floorf(dy);
                int x1 = (int)(L + fdx) + shift;    // trunc == astype(int32)
                int y1 = (int)(L + fdy) + shift;
                x1 = min(max(x1, 0), 5);            // dynamic_slice start clamp
                y1 = min(max(y1, 0), 5);
                bp.off1 = y1 * SW + x1;
                float fx = dx - fdx, fy = dy - fdy;
                bp.fx1 = __float2half2_rn(fx);
                bp.A1  = __float2half2_rn(0.25f * fy);
                bp.B1  = __float2half2_rn(0.25f * (1.0f - fy));
            }
            {
                float dx = dx2[tid], dy = dy2[tid];
                float fdx = floorf(dx), fdy = floorf(dy);
                int x1 = (int)(L + fdx) + shift;
                int y1 = (int)(L + fdy) + shift;
                x1 = min(max(x1, 0), 5);
                y1 = min(max(y1, 0), 5);
                bp.off2 = y1 * SW + x1;
                float fx = dx - fdx, fy = dy - fdy;
                bp.fx2 = __float2half2_rn(fx);
                bp.A2n = __float2half2_rn(-0.25f * fy);
                bp.B2n = __float2half2_rn(-0.25f * (1.0f - fy));
            }
            bp.c = __float2half2_rn(fmaf(-0.25f, th[tid], 0.125f));
            bp.pad0 = bp.pad1 = bp.pad2 = 0;
            g_params[tid] = bp;
        }
    }

    // --- build this (h-tile, image)'s delta pair-tiles ---------------------
    int h0 = blockIdx.x * TH;
    int n  = blockIdx.y;
    const float* src = x + ((size_t)n * 3 + 1) * (HW * HW);
    uint2* gea = g_EA + ((size_t)n * NHT + blockIdx.x) * PAIRS;
    uint2* geb = g_EB + ((size_t)n * NHT + blockIdx.x) * PAIRS;

    for (int j = tid; j < PAIRS; j += NTHR) {
        int r  = j / SW2;
        int c  = j - r * SW2;
        int h  = h0 + r - 3;
        int w0 = 2 * c - 3;
        const float* row = src + h * HW;
        bool hok = (unsigned)h < HW;
        float v0 = 0.0f, v1 = 0.0f, v2 = 0.0f, v3 = 0.0f;
        if (hok) {
            if ((unsigned)w0 < HW)        v0 = row[w0];
            if ((unsigned)(w0 + 1) < HW)  v1 = row[w0 + 1];
            if (c != SW2 - 1) {
                if ((unsigned)(w0 + 2) < HW) v2 = row[w0 + 2];
                if ((unsigned)(w0 + 3) < HW) v3 = row[w0 + 3];
            }
        }
        uint2 ea, eb;
        *(__half2*)&ea.x = __floats2half2_rn(v0, v1);
        *(__half2*)&ea.y = __floats2half2_rn(v1 - v0, v2 - v1);
        *(__half2*)&eb.x = __floats2half2_rn(v1, v2);
        *(__half2*)&eb.y = __floats2half2_rn(v2 - v1, v3 - v2);
        gea[j] = ea;
        geb[j] = eb;
    }
}

// ---------------------------------------------------------------------------
// Main: block = (16-row tile, 16-bit group, image), 320 thr = 80 pairs x 4
// row-groups. Smem fill is now a coalesced uint4 copy from the L2-resident
// precomputed tiles. Software-pipelined double-buffered z (R13 winner).
// ---------------------------------------------------------------------------
__global__ __launch_bounds__(NTHR) void fern_main(float* __restrict__ out) {
    __shared__ __align__(16) uint2 EA[PAIRS];
    __shared__ __align__(16) uint2 EB[PAIRS];
    __shared__ BitH sp[BITG];

    int tid = threadIdx.x;
    int h0  = blockIdx.x * TH;
    int bg  = blockIdx.y;
    int n   = blockIdx.z;

    // params copy: 16 * 48B = 48 uint4
    {
        const uint4* ps = (const uint4*)(g_params + bg * BITG);
        uint4* pd = (uint4*)sp;
        if (tid < BITG * 3) pd[tid] = ps[tid];
    }
    // tile copy: 924 uint4 each
    {
        const uint4* ga = (const uint4*)(g_EA + ((size_t)n * NHT + blockIdx.x) * PAIRS);
        const uint4* gb = (const uint4*)(g_EB + ((size_t)n * NHT + blockIdx.x) * PAIRS);
        uint4* da = (uint4*)EA;
        uint4* db = (uint4*)EB;
        for (int i = tid; i < PAIRS / 2; i += NTHR) {
            da[i] = ga[i];
            db[i] = gb[i];
        }
    }
    __syncthreads();

    int p     = tid % 80;             // column pair
    int wp    = 2 * p;
    int ro0   = (tid / 80) * RR;      // first output row of this thread
    int pbase = p + ro0 * SW2;

    float* op0 = out + (((size_t)n * NBITS + bg * BITG) * HW + h0 + ro0) * HW + wp;

    __half2 z1[2][RR + 1], z2[2][RR + 1];

    // prologue: bit 0 loads + horizontal lerps
    {
        BitH bq = sp[0];
        const uint2* q1 = ((bq.off1 & 1) ? EB : EA) + (bq.off1 >> 1) + pbase;
        const uint2* q2 = ((bq.off2 & 1) ? EB : EA) + (bq.off2 >> 1) + pbase;
#pragma unroll
        for (int r = 0; r <= RR; ++r) {
            uint2 e1 = q1[r * SW2], e2 = q2[r * SW2];
            z1[0][r] = __hfma2(bq.fx1, *(__half2*)&e1.y, *(__half2*)&e1.x);
            z2[0][r] = __hfma2(bq.fx2, *(__half2*)&e2.y, *(__half2*)&e2.x);
        }
    }

#pragma unroll 2
    for (int b = 0; b < BITG; ++b) {
        int cur = b & 1, nxt = cur ^ 1;

        // prefetch + convert next bit (loads issue before current combine)
        {
            int bn = (b + 1 < BITG) ? (b + 1) : b;   // tail: cheap re-read
            BitH bq = sp[bn];
            const uint2* q1 = ((bq.off1 & 1) ? EB : EA) + (bq.off1 >> 1) + pbase;
            const uint2* q2 = ((bq.off2 & 1) ? EB : EA) + (bq.off2 >> 1) + pbase;
#pragma unroll
            for (int r = 0; r <= RR; ++r) {
                uint2 e1 = q1[r * SW2], e2 = q2[r * SW2];
                z1[nxt][r] = __hfma2(bq.fx1, *(__half2*)&e1.y, *(__half2*)&e1.x);
                z2[nxt][r] = __hfma2(bq.fx2, *(__half2*)&e2.y, *(__half2*)&e2.x);
            }
        }

        // combine + store current bit
        BitH bp = sp[b];
        float* op = op0;
        op0 += HW * HW;

#pragma unroll
        for (int hh = 0; hh < RR; ++hh) {
            __half2 v = __hfma2(bp.B1, z1[cur][hh], bp.c);
            v = __hfma2(bp.A1,  z1[cur][hh + 1], v);
            v = __hfma2(bp.B2n, z2[cur][hh], v);
            v = hfma2_sat(bp.A2n, z2[cur][hh + 1], v);

            stcs64(op + (size_t)hh * HW, __half22float2(v));
        }
    }
}

// ---------------------------------------------------------------------------
extern "C" void kernel_launch(void* const* d_in, const int* in_sizes, int n_in,
                              void* d_out, int out_size) {
    const float* x   = (const float*)d_in[0];
    const float* dx1 = (const float*)d_in[1];
    const float* dx2 = (const float*)d_in[2];
    const float* dy1 = (const float*)d_in[3];
    const float* dy2 = (const float*)d_in[4];
    const float* th  = (const float*)d_in[5];

    dim3 pgrid(NHT, NIMG);
    prep_kernel<<<pgrid, NTHR>>>(x, dx1, dx2, dy1, dy2, th);

    dim3 grid(NHT, NBITS / BITG, NIMG);
    fern_main<<<grid, NTHR>>>((float*)d_out);
}

// round 17
// speedup vs baseline: 1.9010x; 1.1251x over previous
#include <cuda_runtime.h>
#include <cuda_fp16.h>

#define HW    160
#define NIMG  32
#define NBITS 128
#define SW    168
#define SW2   (SW / 2)         // 84 pair-entries per row
#define TH    16
#define TROWS 22
#define TILEN (TROWS * SW)     // 3696 column indices
#define PAIRS (TILEN / 2)      // 1848 u64 entries per parity tile
#define BITG  16
#define NTHR  320
#define RR    4                // rows per thread (320 thr = 80 pairs x 4 rgs)

struct __align__(16) BitH {
    __half2 fx1, fx2, B1, A1, B2n, A2n, c;   // 28 B
    int off1, off2;                           // y1*SW + x1 per interp
    int pad;                                  // -> 40 B
};

__device__ __forceinline__ __half2 hfma2_sat(__half2 a, __half2 b, __half2 c) {
    __half2 r;
    asm("fma.rn.sat.f16x2 %0, %1, %2, %3;"
        : "=r"(*(unsigned*)&r)
        : "r"(*(unsigned*)&a), "r"(*(unsigned*)&b), "r"(*(unsigned*)&c));
    return r;
}

__device__ __forceinline__ void stcs64(float* p, float2 v) {
    asm volatile("st.global.cs.v2.f32 [%0], {%1, %2};"
                 :: "l"(p), "f"(v.x), "f"(v.y) : "memory");
}

// ---------------------------------------------------------------------------
// Single fused kernel (R13 structure — the measured optimum). Block =
// (16-row tile, 16-bit group, image), 320 thr = 80 column-pairs x 4 row-
// groups (4 rows each); 2560 blocks.
// Delta pair-tiles: EA[j]=(p[2j],p[2j+1],d[2j],d[2j+1]), EB[j]= same at
// s=2j+1; consecutive lanes hit consecutive u64 entries (dense LDS.64).
// Software pipeline: double-buffered horizontal lerps z[2][RR+1]; the 10
// LDS.64s of bit b+1 issue before the combine+store of bit b. Tail iteration
// skips the dummy prefetch. Fill uses division-free incremental indexing.
// ---------------------------------------------------------------------------
__global__ __launch_bounds__(NTHR) void fern_main(const float* __restrict__ x,
                                                  const float* __restrict__ dx1,
                                                  const float* __restrict__ dx2,
                                                  const float* __restrict__ dy1,
                                                  const float* __restrict__ dy2,
                                                  const float* __restrict__ th,
                                                  float* __restrict__ out) {
    __shared__ __align__(16) uint2 EA[PAIRS];
    __shared__ __align__(16) uint2 EB[PAIRS];
    __shared__ BitH  sp[BITG];
    __shared__ float wred[4];

    int tid = threadIdx.x;
    int h0  = blockIdx.x * TH;
    int bg  = blockIdx.y;
    int n   = blockIdx.z;

    // --- L = max|offset| (warp reductions; identical in every block) -------
    float m = 0.0f;
    if (tid < 128) {
        m = fmaxf(fmaxf(fabsf(dx1[tid]), fabsf(dx2[tid])),
                  fmaxf(fabsf(dy1[tid]), fabsf(dy2[tid])));
    }
#pragma unroll
    for (int o = 16; o; o >>= 1) m = fmaxf(m, __shfl_xor_sync(0xffffffffu, m, o));
    if (tid < 128 && (tid & 31) == 0) wred[tid >> 5] = m;

    // --- fill delta pair-tiles (division-free incremental indexing) --------
    const float* src = x + ((size_t)n * 3 + 1) * (HW * HW);
    {
        int r = tid / SW2;            // one division per THREAD (not entry)
        int c = tid - r * SW2;
        for (int j = tid; j < PAIRS; j += NTHR) {
            int h  = h0 + r - 3;
            int w0 = 2 * c - 3;
            const float* row = src + h * HW;
            bool hok = (unsigned)h < HW;
            float v0 = 0.0f, v1 = 0.0f, v2 = 0.0f, v3 = 0.0f;
            if (hok) {
                if ((unsigned)w0 < HW)        v0 = row[w0];
                if ((unsigned)(w0 + 1) < HW)  v1 = row[w0 + 1];
                if (c != SW2 - 1) {           // c==83: next row's left pad = 0
                    if ((unsigned)(w0 + 2) < HW) v2 = row[w0 + 2];
                    if ((unsigned)(w0 + 3) < HW) v3 = row[w0 + 3];
                }
            }
            uint2 ea, eb;
            *(__half2*)&ea.x = __floats2half2_rn(v0, v1);
            *(__half2*)&ea.y = __floats2half2_rn(v1 - v0, v2 - v1);
            *(__half2*)&eb.x = __floats2half2_rn(v1, v2);
            *(__half2*)&eb.y = __floats2half2_rn(v2 - v1, v3 - v2);
            EA[j] = ea;
            EB[j] = eb;
            // advance j by NTHR = 3 rows + 68 cols (NTHR = 3*SW2 + 68)
            r += 3; c += 68;
            if (c >= SW2) { c -= SW2; r += 1; }
        }
    }
    __syncthreads();

    // --- per-bit params (reference-exact index math) -----------------------
    if (tid < BITG) {
        float L = fmaxf(fmaxf(wred[0], wred[1]), fmaxf(wred[2], wred[3]));
        int shift = 3 - (int)ceilf(L);
        int bit = bg * BITG + tid;
        BitH bp;
        {
            float dx = dx1[bit], dy = dy1[bit];
            float fdx = floorf(dx), fdy = floorf(dy);
            int x1 = (int)(L + fdx) + shift;    // trunc toward zero == astype(int32)
            int y1 = (int)(L + fdy) + shift;
            x1 = min(max(x1, 0), 5);            // dynamic_slice start clamp
            y1 = min(max(y1, 0), 5);
            bp.off1 = y1 * SW + x1;
            float fx = dx - fdx, fy = dy - fdy;
            bp.fx1 = __float2half2_rn(fx);
            bp.A1  = __float2half2_rn(0.25f * fy);
            bp.B1  = __float2half2_rn(0.25f * (1.0f - fy));
        }
        {
            float dx = dx2[bit], dy = dy2[bit];
            float fdx = floorf(dx), fdy = floorf(dy);
            int x1 = (int)(L + fdx) + shift;
            int y1 = (int)(L + fdy) + shift;
            x1 = min(max(x1, 0), 5);
            y1 = min(max(y1, 0), 5);
            bp.off2 = y1 * SW + x1;
            float fx = dx - fdx, fy = dy - fdy;
            bp.fx2 = __float2half2_rn(fx);
            bp.A2n = __float2half2_rn(-0.25f * fy);
            bp.B2n = __float2half2_rn(-0.25f * (1.0f - fy));
        }
        bp.c = __float2half2_rn(fmaf(-0.25f, th[bit], 0.125f));
        bp.pad = 0;
        sp[tid] = bp;
    }
    __syncthreads();

    // --- main loop (software-pipelined over bits) --------------------------
    int p     = tid % 80;             // column pair
    int wp    = 2 * p;
    int ro0   = (tid / 80) * RR;      // first output row of this thread
    int pbase = p + ro0 * SW2;        // uniform per-thread pair offset

    float* op0 = out + (((size_t)n * NBITS + bg * BITG) * HW + h0 + ro0) * HW + wp;

    __half2 z1[2][RR + 1], z2[2][RR + 1];

    // prologue: bit 0 loads + horizontal lerps
    {
        BitH bq = sp[0];
        const uint2* q1 = ((bq.off1 & 1) ? EB : EA) + (bq.off1 >> 1) + pbase;
        const uint2* q2 = ((bq.off2 & 1) ? EB : EA) + (bq.off2 >> 1) + pbase;
#pragma unroll
        for (int r = 0; r <= RR; ++r) {
            uint2 e1 = q1[r * SW2], e2 = q2[r * SW2];
            z1[0][r] = __hfma2(bq.fx1, *(__half2*)&e1.y, *(__half2*)&e1.x);
            z2[0][r] = __hfma2(bq.fx2, *(__half2*)&e2.y, *(__half2*)&e2.x);
        }
    }

#pragma unroll 2
    for (int b = 0; b < BITG; ++b) {
        int cur = b & 1, nxt = cur ^ 1;

        // prefetch + convert next bit (loads issue before current combine);
        // no dummy work on the last iteration
        if (b + 1 < BITG) {
            BitH bq = sp[b + 1];
            const uint2* q1 = ((bq.off1 & 1) ? EB : EA) + (bq.off1 >> 1) + pbase;
            const uint2* q2 = ((bq.off2 & 1) ? EB : EA) + (bq.off2 >> 1) + pbase;
#pragma unroll
            for (int r = 0; r <= RR; ++r) {
                uint2 e1 = q1[r * SW2], e2 = q2[r * SW2];
                z1[nxt][r] = __hfma2(bq.fx1, *(__half2*)&e1.y, *(__half2*)&e1.x);
                z2[nxt][r] = __hfma2(bq.fx2, *(__half2*)&e2.y, *(__half2*)&e2.x);
            }
        }

        // combine + store current bit
        BitH bp = sp[b];
        float* op = op0;
        op0 += HW * HW;

#pragma unroll
        for (int hh = 0; hh < RR; ++hh) {
            __half2 v = __hfma2(bp.B1, z1[cur][hh], bp.c);
            v = __hfma2(bp.A1,  z1[cur][hh + 1], v);
            v = __hfma2(bp.B2n, z2[cur][hh], v);
            v = hfma2_sat(bp.A2n, z2[cur][hh + 1], v);

            stcs64(op + (size_t)hh * HW, __half22float2(v));
        }
    }
}

// ---------------------------------------------------------------------------
extern "C" void kernel_launch(void* const* d_in, const int* in_sizes, int n_in,
                              void* d_out, int out_size) {
    const float* x   = (const float*)d_in[0];
    const float* dx1 = (const float*)d_in[1];
    const float* dx2 = (const float*)d_in[2];
    const float* dy1 = (const float*)d_in[3];
    const float* dy2 = (const float*)d_in[4];
    const float* th  = (const float*)d_in[5];

    dim3 grid(HW / TH, NBITS / BITG, NIMG);
    fern_main<<<grid, NTHR>>>(x, dx1, dx2, dy1, dy2, th, (float*)d_out);
}